// round 4
// baseline (speedup 1.0000x reference)
#include <cuda_runtime.h>
#include <math.h>

#ifndef M_PI
#define M_PI 3.14159265358979323846
#endif

#define NA   1152
#define ND   736
#define NP   512
#define PADN 2048
#define HALF (PADN/2 + 1)

// ---- device scratch (static allocations only) ----
__device__ float  g_filt[HALF];        // rfft half-spectrum filter
__device__ float  g_h[PADN];           // spatial filter kernel (scale folded in)
__device__ float2 g_ang[NA];           // (cos, sin) per angle
__device__ float  g_flt[NA * ND];      // filtered sinogram

// ---------------------------------------------------------------------------
__device__ __forceinline__ double block_reduce128(double v) {
    __shared__ double s[4];
    int lane = threadIdx.x & 31, w = threadIdx.x >> 5;
    #pragma unroll
    for (int o = 16; o > 0; o >>= 1)
        v += __shfl_down_sync(0xffffffffu, v, o);
    if (lane == 0) s[w] = v;
    __syncthreads();
    double t = 0.0;
    if (threadIdx.x == 0) {
        #pragma unroll
        for (int i = 0; i < 4; i++) t += s[i];
    }
    return t;
}

// ---------------------------------------------------------------------------
// FILT[k] = 2*(0.25 + 2*sum_{odd n<=1023} (-1/(pi n)^2) cos(2 pi k n / 2048))
//           * (k==0 ? 1 : sin(pi k/2048)/(pi k/2048))
__global__ void k_filt_coeff() {
    int k = blockIdx.x;  // 0..1024
    double p = 0.0;
    for (int n = 2 * threadIdx.x + 1; n < 1024; n += 256) {
        int m = (k * n) & (PADN - 1);                 // exact reduction mod 2048
        p += cospi((double)m / 1024.0) / ((double)n * (double)n);
    }
    double s = block_reduce128(p);
    if (threadIdx.x == 0) {
        const double inv_pi2 = 1.0 / (M_PI * M_PI);
        double F = 2.0 * (0.25 - 2.0 * inv_pi2 * s);
        if (k > 0) {
            double x = M_PI * (double)k / (double)PADN;
            F *= sin(x) / x;
        }
        g_filt[k] = (float)F;
    }
}

// h[n] = (1/2048)*(FILT[0] + 2*sum_{k=1..1023} FILT[k] cos(2 pi k n/2048)
//        + FILT[1024]*(-1)^n), scaled by pi/(2*NA)
__global__ void k_spatial() {
    int n = blockIdx.x;  // 0..2047
    double p = 0.0;
    for (int k = threadIdx.x + 1; k < PADN / 2; k += 128) {
        int m = (k * n) & (PADN - 1);
        p += (double)g_filt[k] * cospi((double)m / 1024.0);
    }
    double s = block_reduce128(p);
    if (threadIdx.x == 0) {
        double v = (double)g_filt[0] + 2.0 * s
                 + (double)g_filt[PADN / 2] * ((n & 1) ? -1.0 : 1.0);
        v *= (1.0 / (double)PADN) * (M_PI / (2.0 * (double)NA));
        g_h[n] = (float)v;
    }
}

__global__ void k_angles() {
    int a = blockIdx.x * blockDim.x + threadIdx.x;
    if (a < NA) {
        double ang = (2.0 * M_PI / (double)NA) * (double)a + M_PI / 2.0;
        g_ang[a] = make_float2((float)cos(ang), (float)sin(ang));
    }
}

// ---------------------------------------------------------------------------
// Per-row circular convolution: flt[a][j] = sum_m sino[a][m] * h[(j-m) & 2047]
// One block per row. 3 consecutive outputs per thread, rolling h registers.
__global__ void k_conv(const float* __restrict__ sino) {
    __shared__ float s_row[ND];
    __shared__ float s_h[PADN];
    int a = blockIdx.x;
    const float* row = sino + a * ND;
    for (int i = threadIdx.x; i < ND; i += blockDim.x)   s_row[i] = row[i];
    for (int i = threadIdx.x; i < PADN; i += blockDim.x) s_h[i]   = g_h[i];
    __syncthreads();

    int j0 = 3 * threadIdx.x;
    if (j0 >= ND) return;

    float a0 = 0.f, a1 = 0.f, a2 = 0.f;
    float hm  = s_h[j0 & (PADN - 1)];
    float hm1 = s_h[(j0 + 1) & (PADN - 1)];
    float hm2 = s_h[(j0 + 2) & (PADN - 1)];
    #pragma unroll 4
    for (int m = 0; m < ND; m++) {
        float r = s_row[m];
        a0 = fmaf(r, hm,  a0);
        a1 = fmaf(r, hm1, a1);
        a2 = fmaf(r, hm2, a2);
        hm2 = hm1; hm1 = hm;
        hm = s_h[(j0 - m - 1) & (PADN - 1)];
    }
    float* out = g_flt + a * ND;
    out[j0] = a0;
    if (j0 + 1 < ND) out[j0 + 1] = a1;
    if (j0 + 2 < ND) out[j0 + 2] = a2;
}

// ---------------------------------------------------------------------------
// Pixel-driven fan-beam backprojection + HU rescale.
__global__ void k_bp(float* __restrict__ out) {
    __shared__ float2 s_ang[NA];
    for (int t = threadIdx.y * blockDim.x + threadIdx.x; t < NA;
         t += blockDim.x * blockDim.y)
        s_ang[t] = g_ang[t];
    __syncthreads();

    int j = blockIdx.x * blockDim.x + threadIdx.x;  // x (fast dim)
    int i = blockIdx.y * blockDim.y + threadIdx.y;  // y (slow dim)
    float x = (float)j - 255.5f;
    float y = (float)i - 255.5f;

    const float Df = (float)(595.0 / 0.7);                    // D
    const float K  = (float)((595.0 + 490.6) / 1.2858);       // DSD/DU (VOX cancels)
    const float CD = (float)((ND - 1) * 0.5);                 // 367.5

    float acc = 0.0f;
    const float* __restrict__ flt = g_flt;
    for (int a = 0; a < NA; a++) {
        float2 cs = s_ang[a];
        float den  = Df - (x * cs.x + y * cs.y);
        float pe   = y * cs.x - x * cs.y;
        float rcp;
        asm("rcp.approx.f32 %0, %1;" : "=f"(rcp) : "f"(den));
        float iu   = K * pe * rcp + CD;
        float fl   = floorf(iu);
        float frac = iu - fl;
        int   i0   = (int)fl;
        bool  valid = (i0 >= 0) && (i0 < ND - 1);
        int   ic   = min(max(i0, 0), ND - 2);
        const float* rowp = flt + a * ND + ic;
        float v0 = __ldg(rowp);
        float v1 = __ldg(rowp + 1);
        float v  = v0 + frac * (v1 - v0);
        float t  = Df * rcp;
        float w  = t * t;
        acc += valid ? w * v : 0.0f;
    }
    // (1000*((fbp-0.0192)/0.0192) + 1024) / 4096  ==  A*fbp + B
    const float A = (float)(1000.0 / (0.0192 * 4096.0));
    const float B = (float)(24.0 / 4096.0);
    out[i * NP + j] = A * acc + B;
}

// ---------------------------------------------------------------------------
extern "C" void kernel_launch(void* const* d_in, const int* in_sizes, int n_in,
                              void* d_out, int out_size) {
    const float* x = (const float*)d_in[0];   // (1,1,1152,736) f32
    float* out = (float*)d_out;               // (1,1,512,512) f32

    k_filt_coeff<<<HALF, 128>>>();
    k_spatial<<<PADN, 128>>>();
    k_angles<<<(NA + 255) / 256, 256>>>();
    k_conv<<<NA, 256>>>(x);
    dim3 bb(32, 8), gb(NP / 32, NP / 8);
    k_bp<<<gb, bb>>>(out);
}

// round 5
// speedup vs baseline: 1.3166x; 1.3166x over previous
#include <cuda_runtime.h>
#include <math.h>

#ifndef M_PI
#define M_PI 3.14159265358979323846
#endif

#define NA   1152
#define ND   736
#define NP   512
#define PADN 2048
#define HALF (PADN/2 + 1)
#define ESZ  1476      // extended filter: indices j0-m+736, j0 in [0,738), m in [0,736)

// ---- device scratch (static allocations only) ----
__device__ float  g_filt[HALF];        // rfft half-spectrum filter
__device__ float  g_h[PADN];           // spatial filter kernel (scale folded in)
__device__ float2 g_ang[NA];           // (cos, sin) per angle
__device__ float  g_flt[NA * ND];      // filtered sinogram

// ---------------------------------------------------------------------------
__device__ __forceinline__ double block_reduce128(double v) {
    __shared__ double s[4];
    int lane = threadIdx.x & 31, w = threadIdx.x >> 5;
    #pragma unroll
    for (int o = 16; o > 0; o >>= 1)
        v += __shfl_down_sync(0xffffffffu, v, o);
    if (lane == 0) s[w] = v;
    __syncthreads();
    double t = 0.0;
    if (threadIdx.x == 0) {
        #pragma unroll
        for (int i = 0; i < 4; i++) t += s[i];
    }
    return t;
}

// ---------------------------------------------------------------------------
// FILT[k] = 2*(0.25 + 2*sum_{odd n<=1023} (-1/(pi n)^2) cos(2 pi k n / 2048))
//           * (k==0 ? 1 : sin(pi k/2048)/(pi k/2048))
// fp32 cospif with exact argument reduction (m/1024 exact), fp64 accumulate.
__global__ void k_filt_coeff() {
    int k = blockIdx.x;  // 0..1024
    double p = 0.0;
    for (int n = 2 * threadIdx.x + 1; n < 1024; n += 256) {
        int m = (k * n) & (PADN - 1);                 // exact reduction mod 2048
        float c = cospif((float)m * (1.0f / 1024.0f));
        p += (double)(c / ((float)n * (float)n));
    }
    double s = block_reduce128(p);
    if (threadIdx.x == 0) {
        const double inv_pi2 = 1.0 / (M_PI * M_PI);
        double F = 2.0 * (0.25 - 2.0 * inv_pi2 * s);
        if (k > 0) {
            double x = M_PI * (double)k / (double)PADN;
            F *= sin(x) / x;
        }
        g_filt[k] = (float)F;
    }
}

// h[n] = (1/2048)*(FILT[0] + 2*sum_{k=1..1023} FILT[k] cos(2 pi k n/2048)
//        + FILT[1024]*(-1)^n), scaled by pi/(2*NA)
__global__ void k_spatial() {
    int n = blockIdx.x;  // 0..2047
    double p = 0.0;
    for (int k = threadIdx.x + 1; k < PADN / 2; k += 128) {
        int m = (k * n) & (PADN - 1);
        float c = cospif((float)m * (1.0f / 1024.0f));
        p += (double)(g_filt[k] * c);
    }
    double s = block_reduce128(p);
    if (threadIdx.x == 0) {
        double v = (double)g_filt[0] + 2.0 * s
                 + (double)g_filt[PADN / 2] * ((n & 1) ? -1.0 : 1.0);
        v *= (1.0 / (double)PADN) * (M_PI / (2.0 * (double)NA));
        g_h[n] = (float)v;
    }
}

__global__ void k_angles() {
    int a = blockIdx.x * blockDim.x + threadIdx.x;
    if (a < NA) {
        double ang = (2.0 * M_PI / (double)NA) * (double)a + M_PI / 2.0;
        g_ang[a] = make_float2((float)cos(ang), (float)sin(ang));
    }
}

// ---------------------------------------------------------------------------
// Per-row circular convolution: flt[a][j] = sum_m sino[a][m] * h[(j-m) & 2047]
// One block per row. 3 consecutive outputs per thread (stride-3 h access is
// bank-conflict-free), rolling h registers, extended filter array so the
// inner loop has NO address arithmetic (pure LDS [r+imm] + FMA).
__global__ void __launch_bounds__(256) k_conv(const float* __restrict__ sino) {
    __shared__ float s_row[ND];
    __shared__ float s_e[ESZ];          // s_e[i] = h[(i - 736) mod 2048]
    int a = blockIdx.x;
    const float* row = sino + a * ND;
    for (int i = threadIdx.x; i < ND; i += blockDim.x)  s_row[i] = row[i];
    for (int i = threadIdx.x; i < ESZ; i += blockDim.x) s_e[i] = g_h[(i + 1312) & (PADN - 1)];
    __syncthreads();

    int j0 = 3 * threadIdx.x;
    if (j0 >= ND) return;
    const float* e = s_e + (j0 + 736);  // e[-m] = h[(j0-m) & 2047]

    float a0 = 0.f, a1 = 0.f, a2 = 0.f;
    float hm  = e[0];
    float hm1 = e[1];
    float hm2 = e[2];
    #pragma unroll 4
    for (int m = 0; m < ND; m++) {
        float r = s_row[m];
        a0 = fmaf(r, hm,  a0);
        a1 = fmaf(r, hm1, a1);
        a2 = fmaf(r, hm2, a2);
        hm2 = hm1; hm1 = hm;
        hm = e[-m - 1];
    }
    float* out = g_flt + a * ND + j0;
    out[0] = a0;
    if (j0 + 1 < ND) out[1] = a1;
    if (j0 + 2 < ND) out[2] = a2;
}

// ---------------------------------------------------------------------------
// Pixel-driven fan-beam backprojection + HU rescale.
// 4 angles per iteration: batch the 8 gathers to expose MLP, 4 accumulators.
__global__ void __launch_bounds__(256) k_bp(float* __restrict__ out) {
    __shared__ float2 s_ang[NA];
    for (int t = threadIdx.y * blockDim.x + threadIdx.x; t < NA;
         t += blockDim.x * blockDim.y)
        s_ang[t] = g_ang[t];
    __syncthreads();

    int j = blockIdx.x * blockDim.x + threadIdx.x;  // x (fast dim)
    int i = blockIdx.y * blockDim.y + threadIdx.y;  // y (slow dim)
    float x = (float)j - 255.5f;
    float y = (float)i - 255.5f;

    const float Df = (float)(595.0 / 0.7);                    // D
    const float K  = (float)((595.0 + 490.6) / 1.2858);       // DSD/DU (VOX cancels)
    const float CD = (float)((ND - 1) * 0.5);                 // 367.5

    const float* __restrict__ flt = g_flt;
    float acc0 = 0.f, acc1 = 0.f, acc2 = 0.f, acc3 = 0.f;

    for (int a = 0; a < NA; a += 4) {
        int   off[4];
        float fr[4], wv[4];
        #pragma unroll
        for (int q = 0; q < 4; q++) {
            float2 cs = s_ang[a + q];
            float den = Df - x * cs.x - y * cs.y;
            float pe  = y * cs.x - x * cs.y;
            float rcp;
            asm("rcp.approx.f32 %0, %1;" : "=f"(rcp) : "f"(den));
            float iu = fmaf(K * pe, rcp, CD);
            int i0 = __float2int_rd(iu);
            fr[q] = iu - __int2float_rn(i0);
            int ic = min(max(i0, 0), ND - 2);
            off[q] = (a + q) * ND + ic;
            float t = Df * rcp;
            wv[q] = ((unsigned)i0 <= (unsigned)(ND - 2)) ? t * t : 0.f;
        }
        float v[8];
        #pragma unroll
        for (int q = 0; q < 4; q++) {
            v[2 * q]     = __ldg(flt + off[q]);
            v[2 * q + 1] = __ldg(flt + off[q] + 1);
        }
        acc0 = fmaf(wv[0], fmaf(fr[0], v[1] - v[0], v[0]), acc0);
        acc1 = fmaf(wv[1], fmaf(fr[1], v[3] - v[2], v[2]), acc1);
        acc2 = fmaf(wv[2], fmaf(fr[2], v[5] - v[4], v[4]), acc2);
        acc3 = fmaf(wv[3], fmaf(fr[3], v[7] - v[6], v[6]), acc3);
    }
    float acc = (acc0 + acc1) + (acc2 + acc3);

    // (1000*((fbp-0.0192)/0.0192) + 1024) / 4096  ==  A*fbp + B
    const float A = (float)(1000.0 / (0.0192 * 4096.0));
    const float B = (float)(24.0 / 4096.0);
    out[i * NP + j] = fmaf(A, acc, B);
}

// ---------------------------------------------------------------------------
extern "C" void kernel_launch(void* const* d_in, const int* in_sizes, int n_in,
                              void* d_out, int out_size) {
    const float* x = (const float*)d_in[0];   // (1,1,1152,736) f32
    float* out = (float*)d_out;               // (1,1,512,512) f32

    k_filt_coeff<<<HALF, 128>>>();
    k_spatial<<<PADN, 128>>>();
    k_angles<<<(NA + 255) / 256, 256>>>();
    k_conv<<<NA, 256>>>(x);
    dim3 bb(32, 8), gb(NP / 32, NP / 8);
    k_bp<<<gb, bb>>>(out);
}